// round 3
// baseline (speedup 1.0000x reference)
#include <cuda_runtime.h>
#include <cstdlib>
#include <cfloat>

#define BB 8
#define NN 2048
#define KNB 20
#define NEGS 0.2f
#define EPSB 1e-5f

__attribute__((constructor)) static void _eager_load(){ setenv("CUDA_MODULE_LOADING","EAGER",0); }

// ------------------------- scratch (device globals) -------------------------
__device__ float g_xT  [(size_t)BB*NN*256];        // point-major features of current layer input
__device__ float g_xx  [BB*NN];                    // per-point squared norm
__device__ float g_dist[(size_t)BB*NN*NN];         // neg pairwise distances
__device__ int   g_idx [(size_t)BB*NN*KNB];        // knn indices
__device__ float g_G   [(size_t)BB*NN*KNB*256];    // edge features [B, N*K, 2C] = [nbr-ctr, ctr]
__device__ float g_s   [(size_t)BB*256*NN*KNB];    // W @ f  [B, O, N*K]
__device__ float g_kmax[(size_t)BB*256*NN];
__device__ float g_kmin[(size_t)BB*256*NN];
__device__ float g_ksum[(size_t)BB*256*NN];
__device__ float g_ksq [(size_t)BB*256*NN];
__device__ float g_xcat[(size_t)BB*512*NN];        // concat(x1,x2,x3,x4) channel-major
__device__ float g_h5  [(size_t)BB*1024*NN];       // pre-BN conv5 output
__device__ float g_hb1 [(size_t)BB*256*NN];
__device__ float g_hb2 [(size_t)BB*256*NN];
__device__ float g_hb3 [(size_t)BB*128*NN];
__device__ float g_glob[BB*1088];                  // [gmax(1024), lf(64)]
__device__ float g_b207[BB*256];                   // per-(b,o) bias from global channels of W207
__device__ float g_prm [2048];                     // per-channel BN (mean, var)

// ------------------------- generic fp32 GEMM -------------------------
// Accumulation: single accumulator per output, FMA, k strictly ascending
// (matches cuBLAS fp32 sgemm semantics).
// out[b, m, n] = sum_k A[m,k] * B(b)[n,k]           (BT=false: B row-major JxK)
//             or sum_k A[m,k] * B(b)[k,n]           (BT=true : B is KxJ, ldb = row stride)
// MODE 0: plain store
// MODE 1: dist epilogue: v = 2*acc - e0[b*NN+m] - e0[b*NN+n]   (exact ref op order)
// MODE 2: row bias:      v = acc + e0[b*M+m]
template<bool BT, int MODE>
__global__ void __launch_bounds__(256) k_gemm(
    int M, int Ncol, int Kd,
    const float* __restrict__ A, int lda, size_t asb,
    const float* __restrict__ Bp, int ldb, size_t bsb,
    float* __restrict__ Cp, size_t csb,
    const float* __restrict__ e0)
{
    const int BM=128, BN=128, BK=16;
    __shared__ float As[BK][BM+4];
    __shared__ float Bs[BK][BN+4];
    int b  = blockIdx.z;
    int m0 = blockIdx.y*BM, n0 = blockIdx.x*BN;
    A  += (size_t)b*asb;
    Bp += (size_t)b*bsb;
    Cp += (size_t)b*csb;
    int tid = threadIdx.x;
    int tx = tid%16, ty = tid/16;

    float acc[8][8];
    #pragma unroll
    for(int i=0;i<8;i++)
        #pragma unroll
        for(int j=0;j<8;j++) acc[i][j]=0.f;

    for(int k0=0;k0<Kd;k0+=BK){
        #pragma unroll
        for(int i=tid;i<BM*BK;i+=256){
            int kk=i%BK, mm=i/BK;
            int gm=m0+mm, gk=k0+kk;
            As[kk][mm] = (gm<M && gk<Kd) ? A[(size_t)gm*lda+gk] : 0.f;
        }
        if(!BT){
            #pragma unroll
            for(int i=tid;i<BN*BK;i+=256){
                int kk=i%BK, nn=i/BK;
                int gn=n0+nn, gk=k0+kk;
                Bs[kk][nn] = (gn<Ncol && gk<Kd) ? Bp[(size_t)gn*ldb+gk] : 0.f;
            }
        } else {
            #pragma unroll
            for(int i=tid;i<BN*BK;i+=256){
                int nn=i%BN, kk=i/BN;
                int gn=n0+nn, gk=k0+kk;
                Bs[kk][nn] = (gn<Ncol && gk<Kd) ? Bp[(size_t)gk*ldb+gn] : 0.f;
            }
        }
        __syncthreads();
        #pragma unroll
        for(int kk=0;kk<BK;kk++){   // ascending k, FMA, single accumulator
            float a8[8], b8[8];
            #pragma unroll
            for(int i=0;i<8;i++) a8[i]=As[kk][ty*8+i];
            #pragma unroll
            for(int j=0;j<8;j++) b8[j]=Bs[kk][tx*8+j];
            #pragma unroll
            for(int i=0;i<8;i++)
                #pragma unroll
                for(int j=0;j<8;j++) acc[i][j] = __fmaf_rn(a8[i], b8[j], acc[i][j]);
        }
        __syncthreads();
    }
    #pragma unroll
    for(int i=0;i<8;i++){
        int gm = m0+ty*8+i;
        if(gm>=M) continue;
        #pragma unroll
        for(int j=0;j<8;j++){
            int gn = n0+tx*8+j;
            if(gn>=Ncol) continue;
            float v = acc[i][j];
            if(MODE==1)
                v = __fsub_rn(__fsub_rn(__fmul_rn(2.0f, v), e0[(size_t)b*NN+gm]), e0[(size_t)b*NN+gn]);
            else if(MODE==2)
                v = __fadd_rn(v, e0[(size_t)b*M+gm]);
            Cp[(size_t)gm*Ncol + gn] = v;
        }
    }
}

// ------------------------- small kernels -------------------------

// x [B,3,N] -> g_xT [B,N,3]
__global__ void k_tin(const float* __restrict__ x){
    int i = blockIdx.x*blockDim.x + threadIdx.x;
    if(i >= BB*NN*3) return;
    int c = i%3; int n = (i/3)%NN; int b = i/(3*NN);
    g_xT[i] = x[((size_t)b*3 + c)*NN + n];
}

// per-point squared norm: square elementwise then reduce ascending-c with
// plain adds (matches jnp.sum(x*x, axis=1) lowering order).
__global__ void k_xx(int C){
    int p = blockIdx.x*blockDim.x + threadIdx.x;
    if(p >= BB*NN) return;
    const float* v = g_xT + (size_t)p*C;
    float s = 0.f;
    for(int c=0;c<C;c++) s = __fadd_rn(s, __fmul_rn(v[c], v[c]));
    g_xx[p] = s;
}

// top-K (largest) per row of g_dist, min-index tiebreak (matches lax.top_k)
__global__ void k_topk(){
    int n = blockIdx.x, b = blockIdx.y;
    const float* row = g_dist + ((size_t)b*NN + n)*NN;
    __shared__ float sv[NN];
    __shared__ float bv[256];
    __shared__ int   bi[256];
    int tid = threadIdx.x;
    for(int i=tid;i<NN;i+=256) sv[i]=row[i];
    __syncthreads();
    for(int j=0;j<KNB;j++){
        float best=-FLT_MAX; int besti=NN;
        for(int i=tid;i<NN;i+=256){
            float v=sv[i];
            if(v>best){ best=v; besti=i; }
        }
        bv[tid]=best; bi[tid]=besti;
        __syncthreads();
        for(int st=128;st;st>>=1){
            if(tid<st){
                float v2=bv[tid+st]; int i2=bi[tid+st];
                if(v2>bv[tid] || (v2==bv[tid] && i2<bi[tid])){ bv[tid]=v2; bi[tid]=i2; }
            }
            __syncthreads();
        }
        if(tid==0){
            g_idx[((size_t)b*NN+n)*KNB + j] = bi[0];
            sv[bi[0]] = -FLT_MAX;
        }
        __syncthreads();
    }
}

// G[b, n*K+k, :] = [ xT[idx] - xT[n]  (C),  xT[n]  (C) ]
__global__ void k_gather(int C){
    int C2 = 2*C;
    size_t e = (size_t)blockIdx.x*blockDim.x + threadIdx.x;
    size_t total = (size_t)BB*NN*KNB*C2;
    if(e>=total) return;
    int c = (int)(e % C2);
    size_t r = e / C2;
    int k = (int)(r % KNB);
    int n = (int)((r/KNB) % NN);
    int b = (int)(r/((size_t)KNB*NN));
    int cc = (c < C) ? c : (c - C);
    float ctr = g_xT[((size_t)b*NN + n)*C + cc];
    float val;
    if(c < C){
        int m = g_idx[((size_t)b*NN+n)*KNB + k];
        val = __fsub_rn(g_xT[((size_t)b*NN + m)*C + cc], ctr);
    } else {
        val = ctr;
    }
    g_G[e] = val;
}

// reduce k -> max/min/sum/sumsq over h = s[b,o,n,:]
__global__ void k_kreduce(const float* __restrict__ s, int O){
    size_t p = (size_t)blockIdx.x*blockDim.x + threadIdx.x;
    size_t total = (size_t)BB*O*NN;
    if(p>=total) return;
    const float* sp = s + p*KNB;
    float mx=-FLT_MAX, mn=FLT_MAX, sm=0.f, sq=0.f;
    #pragma unroll
    for(int k=0;k<KNB;k++){
        float h = sp[k];
        mx = fmaxf(mx,h); mn = fminf(mn,h);
        sm = __fadd_rn(sm,h); sq = __fmaf_rn(h,h,sq);
    }
    g_kmax[p]=mx; g_kmin[p]=mn; g_ksum[p]=sm; g_ksq[p]=sq;
}

// per-channel BN mean/var from ksum/ksq; count = B*N*K
// (double stats are fine: mean/var are SHARED per channel -> coherent per-channel
//  shifts cancel in pairwise distances, so no ranking sensitivity.)
__global__ void k_ec_stats(int O){
    int o = blockIdx.x, tid = threadIdx.x;
    double s=0.0, ss=0.0;
    for(int b=0;b<BB;b++){
        size_t base = ((size_t)b*O + o)*NN;
        for(int n=tid;n<NN;n+=256){ s += g_ksum[base+n]; ss += g_ksq[base+n]; }
    }
    __shared__ double rs[256], rq[256];
    rs[tid]=s; rq[tid]=ss; __syncthreads();
    for(int st=128;st;st>>=1){ if(tid<st){ rs[tid]+=rs[tid+st]; rq[tid]+=rq[tid+st]; } __syncthreads(); }
    if(tid==0){
        double cnt = (double)BB*NN*KNB;
        double mean = rs[0]/cnt;
        double var  = rq[0]/cnt - mean*mean;
        g_prm[2*o]   = (float)mean;
        g_prm[2*o+1] = (float)var;
    }
}

// y = lrelu(((kmax - m)/sqrt(v+eps))*g + b)  -- exact reference op order.
// max/BN/lrelu commute bit-exactly (all ops monotone non-decreasing under rounding).
__global__ void k_ec_apply(int O, int c0, float* __restrict__ xTout,
                           const float* __restrict__ gw, const float* __restrict__ bw){
    int o = blockIdx.x, b = blockIdx.y;
    float m = g_prm[2*o], vv = g_prm[2*o+1];
    float gg = gw[o], bb = bw[o];
    float sd = __fsqrt_rn(__fadd_rn(vv, EPSB));
    const float* src = (gg>=0.f ? g_kmax : g_kmin) + ((size_t)b*O + o)*NN;
    float* xc = g_xcat + ((size_t)b*512 + c0 + o)*NN;
    for(int n=threadIdx.x;n<NN;n+=blockDim.x){
        float y = __fadd_rn(__fmul_rn(__fdiv_rn(__fsub_rn(src[n], m), sd), gg), bb);
        y = (y>=0.f) ? y : __fmul_rn(NEGS, y);
        xc[n] = y;
        xTout[((size_t)b*NN + n)*O + o] = y;
    }
}

// BN mean/var for conv1d pre-activations [B,O,N]; count = B*N
__global__ void k_conv_stats(const float* __restrict__ h, int O){
    int o = blockIdx.x, tid = threadIdx.x;
    double s=0.0, ss=0.0;
    for(int b=0;b<BB;b++){
        size_t base = ((size_t)b*O + o)*NN;
        for(int n=tid;n<NN;n+=256){ float v=h[base+n]; s += v; ss += (double)v*v; }
    }
    __shared__ double rs[256], rq[256];
    rs[tid]=s; rq[tid]=ss; __syncthreads();
    for(int st=128;st;st>>=1){ if(tid<st){ rs[tid]+=rs[tid+st]; rq[tid]+=rq[tid+st]; } __syncthreads(); }
    if(tid==0){
        double cnt = (double)BB*NN;
        double mean = rs[0]/cnt;
        double var  = rq[0]/cnt - mean*mean;
        g_prm[2*o]   = (float)mean;
        g_prm[2*o+1] = (float)var;
    }
}

// in-place y = lrelu(((h-m)/sqrt(v+eps))*g + b)
__global__ void k_conv_apply(float* __restrict__ h, int O,
                             const float* __restrict__ gw, const float* __restrict__ bw){
    int o = blockIdx.x, b = blockIdx.y;
    float m = g_prm[2*o], vv = g_prm[2*o+1];
    float gg = gw[o], bb = bw[o];
    float sd = __fsqrt_rn(__fadd_rn(vv, EPSB));
    float* p = h + ((size_t)b*O + o)*NN;
    for(int n=threadIdx.x;n<NN;n+=blockDim.x){
        float y = __fadd_rn(__fmul_rn(__fdiv_rn(__fsub_rn(p[n], m), sd), gg), bb);
        p[n] = (y>=0.f) ? y : __fmul_rn(NEGS, y);
    }
}

// glob[b,o] = lrelu(bn(max_n h5)) (monotone commutation, exact op order)
__global__ void k_gmax(const float* __restrict__ gw, const float* __restrict__ bw){
    int o = blockIdx.x, b = blockIdx.y, tid = threadIdx.x;
    float gg = gw[o];
    const float* p = g_h5 + ((size_t)b*1024 + o)*NN;
    float m = -FLT_MAX, mn = FLT_MAX;
    for(int n=tid;n<NN;n+=256){
        float v = p[n];
        m = fmaxf(m, v); mn = fminf(mn, v);
    }
    __shared__ float r[256], r2[256];
    r[tid]=m; r2[tid]=mn; __syncthreads();
    for(int st=128;st;st>>=1){
        if(tid<st){ r[tid]=fmaxf(r[tid], r[tid+st]); r2[tid]=fminf(r2[tid], r2[tid+st]); }
        __syncthreads();
    }
    if(tid==0){
        float src = (gg>=0.f) ? r[0] : r2[0];
        float mm = g_prm[2*o], vv = g_prm[2*o+1];
        float sd = __fsqrt_rn(__fadd_rn(vv, EPSB));
        float y = __fadd_rn(__fmul_rn(__fdiv_rn(__fsub_rn(src, mm), sd), gg), bw[o]);
        y = (y>=0.f) ? y : __fmul_rn(NEGS, y);
        g_glob[b*1088 + o] = y;
    }
}

// label branch: lf = lrelu(bn(W206 @ l)), BN over batch only, ref op order
__global__ void k_lf(const float* __restrict__ l, const float* __restrict__ W,
                     const float* __restrict__ gw, const float* __restrict__ bw){
    int tid = threadIdx.x;
    int o = tid & 63, b = tid >> 6;   // 512 threads = 8 x 64
    __shared__ float hs[8][64];
    __shared__ float pm[64], pv[64];
    float s = 0.f;
    #pragma unroll
    for(int c=0;c<16;c++) s = __fmaf_rn(W[o*16 + c], l[b*16 + c], s);
    hs[b][o] = s;
    __syncthreads();
    if(tid < 64){
        float m = 0.f;
        #pragma unroll
        for(int q=0;q<8;q++) m = __fadd_rn(m, hs[q][tid]);
        m = __fdiv_rn(m, 8.f);
        float v = 0.f;
        #pragma unroll
        for(int q=0;q<8;q++){ float d = __fsub_rn(hs[q][tid], m); v = __fmaf_rn(d, d, v); }
        v = __fdiv_rn(v, 8.f);
        pm[tid] = m; pv[tid] = v;
    }
    __syncthreads();
    float sd = __fsqrt_rn(__fadd_rn(pv[o], EPSB));
    float y = __fadd_rn(__fmul_rn(__fdiv_rn(__fsub_rn(hs[b][o], pm[o]), sd), gw[o]), bw[o]);
    y = (y>=0.f) ? y : __fmul_rn(NEGS, y);
    g_glob[b*1088 + 1024 + o] = y;
}

// bias207[b,o] = W207[o, 0:1088] . glob[b]  (ascending c, FMA)
__global__ void k_bias207(const float* __restrict__ W207){
    int b = blockIdx.x;
    __shared__ float gl[1088];
    for(int i=threadIdx.x;i<1088;i+=256) gl[i] = g_glob[b*1088 + i];
    __syncthreads();
    int o = threadIdx.x;
    float s = 0.f;
    for(int c=0;c<1088;c++) s = __fmaf_rn(W207[(size_t)o*1600 + c], gl[c], s);
    g_b207[b*256 + o] = s;
}

// ------------------------- launcher -------------------------
extern "C" void kernel_launch(void* const* d_in, const int* in_sizes, int n_in,
                              void* d_out, int out_size){
    (void)in_sizes; (void)n_in; (void)out_size;
    const float* x    = (const float*)d_in[0];
    const float* l    = (const float*)d_in[1];
    const float* Wec[4] = {(const float*)d_in[2],(const float*)d_in[5],(const float*)d_in[8],(const float*)d_in[11]};
    const float* gec[4] = {(const float*)d_in[3],(const float*)d_in[6],(const float*)d_in[9],(const float*)d_in[12]};
    const float* bec[4] = {(const float*)d_in[4],(const float*)d_in[7],(const float*)d_in[10],(const float*)d_in[13]};
    const float* W5   = (const float*)d_in[14]; const float* g5v  = (const float*)d_in[15]; const float* b5v  = (const float*)d_in[16];
    const float* W206 = (const float*)d_in[17]; const float* g206 = (const float*)d_in[18]; const float* b206 = (const float*)d_in[19];
    const float* W207 = (const float*)d_in[20]; const float* g207 = (const float*)d_in[21]; const float* b207 = (const float*)d_in[22];
    const float* W208 = (const float*)d_in[23]; const float* g208 = (const float*)d_in[24]; const float* b208 = (const float*)d_in[25];
    const float* W209 = (const float*)d_in[26]; const float* g209 = (const float*)d_in[27]; const float* b209 = (const float*)d_in[28];
    const float* W2010= (const float*)d_in[29];

    float *xT,*xxp,*dist,*G,*sbuf,*xcat,*h5,*hb1,*hb2,*hb3,*b207p;
    cudaGetSymbolAddress((void**)&xT,   g_xT);
    cudaGetSymbolAddress((void**)&xxp,  g_xx);
    cudaGetSymbolAddress((void**)&dist, g_dist);
    cudaGetSymbolAddress((void**)&G,    g_G);
    cudaGetSymbolAddress((void**)&sbuf, g_s);
    cudaGetSymbolAddress((void**)&xcat, g_xcat);
    cudaGetSymbolAddress((void**)&h5,   g_h5);
    cudaGetSymbolAddress((void**)&hb1,  g_hb1);
    cudaGetSymbolAddress((void**)&hb2,  g_hb2);
    cudaGetSymbolAddress((void**)&hb3,  g_hb3);
    cudaGetSymbolAddress((void**)&b207p,g_b207);

    const int Cin[4] = {3,64,64,128};
    const int Oo [4] = {64,64,128,256};
    const int c0 [4] = {0,64,128,256};

    k_tin<<<(BB*NN*3 + 255)/256, 256>>>(x);

    for(int li=0; li<4; li++){
        int C = Cin[li], O = Oo[li];
        // kNN
        k_xx<<<(BB*NN + 255)/256, 256>>>(C);
        k_gemm<false,1><<<dim3(NN/128, NN/128, BB), 256>>>(
            NN, NN, C, xT, C, (size_t)NN*C, xT, C, (size_t)NN*C, dist, (size_t)NN*NN, xxp);
        k_topk<<<dim3(NN, BB), 256>>>();
        // gather edge features [nbr-ctr, ctr]  (2C channels)
        int C2 = 2*C;
        size_t tot = (size_t)BB*NN*KNB*C2;
        k_gather<<<(unsigned)((tot + 255)/256), 256>>>(C);
        // h = W @ f   (O x (N*K) per batch, K-dim = 2C)
        int J = NN*KNB;
        k_gemm<false,0><<<dim3(J/128, (O+127)/128, BB), 256>>>(
            O, J, C2, Wec[li], C2, 0, G, C2, (size_t)J*C2, sbuf, (size_t)O*J, nullptr);
        // reduce over k, BN stats, apply
        size_t tp = (size_t)BB*O*NN;
        k_kreduce<<<(unsigned)((tp + 255)/256), 256>>>(sbuf, O);
        k_ec_stats<<<O, 256>>>(O);
        k_ec_apply<<<dim3(O, BB), 256>>>(O, c0[li], xT, gec[li], bec[li]);
    }

    // conv5 (1024 x 512) on xcat, then global max
    k_gemm<true,0><<<dim3(NN/128, 1024/128, BB), 256>>>(
        1024, NN, 512, W5, 512, 0, xcat, NN, (size_t)512*NN, h5, (size_t)1024*NN, nullptr);
    k_conv_stats<<<1024, 256>>>(h5, 1024);
    k_gmax<<<dim3(1024, BB), 256>>>(g5v, b5v);
    // label branch
    k_lf<<<1, 512>>>(l, W206, g206, b206);
    // per-(b,o) bias from global channels of W207
    k_bias207<<<BB, 256>>>(W207);
    // conv207: only the 512 point-dependent channels in the GEMM
    k_gemm<true,2><<<dim3(NN/128, 2, BB), 256>>>(
        256, NN, 512, W207 + 1088, 1600, 0, xcat, NN, (size_t)512*NN, hb1, (size_t)256*NN, b207p);
    k_conv_stats<<<256, 256>>>(hb1, 256);
    k_conv_apply<<<dim3(256, BB), 256>>>(hb1, 256, g207, b207);
    // conv208
    k_gemm<true,0><<<dim3(NN/128, 2, BB), 256>>>(
        256, NN, 256, W208, 256, 0, hb1, NN, (size_t)256*NN, hb2, (size_t)256*NN, nullptr);
    k_conv_stats<<<256, 256>>>(hb2, 256);
    k_conv_apply<<<dim3(256, BB), 256>>>(hb2, 256, g208, b208);
    // conv209
    k_gemm<true,0><<<dim3(NN/128, 1, BB), 256>>>(
        128, NN, 256, W209, 256, 0, hb2, NN, (size_t)256*NN, hb3, (size_t)128*NN, nullptr);
    k_conv_stats<<<128, 256>>>(hb3, 128);
    k_conv_apply<<<dim3(128, BB), 256>>>(hb3, 128, g209, b209);
    // final projection (50 x 128), no BN/activation
    k_gemm<true,0><<<dim3(NN/128, 1, BB), 256>>>(
        50, NN, 128, W2010, 128, 0, hb3, NN, (size_t)128*NN, (float*)d_out, (size_t)50*NN, nullptr);
}

// round 5
// speedup vs baseline: 1.2407x; 1.2407x over previous
#include <cuda_runtime.h>
#include <cstdlib>
#include <cfloat>

#define BB 8
#define NN 2048
#define KNB 20
#define NEGS 0.2f
#define EPSB 1e-5f

__attribute__((constructor)) static void _eager_load(){ setenv("CUDA_MODULE_LOADING","EAGER",0); }

// ------------------------- scratch (device globals) -------------------------
__device__ float g_xT  [(size_t)BB*NN*256];
__device__ float g_xx  [BB*NN];
__device__ float g_dist[(size_t)BB*NN*NN];
__device__ int   g_idx [(size_t)BB*NN*KNB];
__device__ float g_G   [(size_t)BB*NN*KNB*256];
__device__ float g_s   [(size_t)BB*256*NN*KNB];
__device__ float g_kmax[(size_t)BB*256*NN];
__device__ float g_kmin[(size_t)BB*256*NN];
__device__ float g_ksum[(size_t)BB*256*NN];
__device__ float g_ksq [(size_t)BB*256*NN];
__device__ float g_xcat[(size_t)BB*512*NN];
__device__ float g_h5  [(size_t)BB*1024*NN];
__device__ float g_hb1 [(size_t)BB*256*NN];
__device__ float g_hb2 [(size_t)BB*256*NN];
__device__ float g_hb3 [(size_t)BB*128*NN];
__device__ float g_glob[BB*1088];
__device__ float g_b207[BB*256];
__device__ float g_prm [2048];

// ------------------------- generic fp32 GEMM (pipelined, bit-identical math) --
// Accumulation: single accumulator per output, FMA, k strictly ascending.
// MODE 0: plain   MODE 1: dist epilogue   MODE 2: row bias
template<bool BT, int MODE>
__global__ void __launch_bounds__(256,2) k_gemm(
    int M, int Ncol, int Kd,
    const float* __restrict__ A, int lda, size_t asb,
    const float* __restrict__ Bp, int ldb, size_t bsb,
    float* __restrict__ Cp, size_t csb,
    const float* __restrict__ e0)
{
    const int BM=128, BN=128, BK=16;
    __shared__ float As[2][BK][BM+4];
    __shared__ float Bs[2][BK][BN+4];
    int b  = blockIdx.z;
    int m0 = blockIdx.y*BM, n0 = blockIdx.x*BN;
    A  += (size_t)b*asb;
    Bp += (size_t)b*bsb;
    Cp += (size_t)b*csb;
    int tid = threadIdx.x;
    int tx = tid%16, ty = tid/16;

    float acc[8][8];
    #pragma unroll
    for(int i=0;i<8;i++)
        #pragma unroll
        for(int j=0;j<8;j++) acc[i][j]=0.f;

    float ra[8], rb[8];

    auto fetchA = [&](int k0){
        #pragma unroll
        for(int i=0;i<8;i++){
            int e = tid + 256*i;
            int kk=e%BK, mm=e/BK;
            int gm=m0+mm, gk=k0+kk;
            ra[i] = (gm<M && gk<Kd) ? A[(size_t)gm*lda+gk] : 0.f;
        }
    };
    auto fetchB = [&](int k0){
        if(!BT){
            #pragma unroll
            for(int i=0;i<8;i++){
                int e = tid + 256*i;
                int kk=e%BK, nn=e/BK;
                int gn=n0+nn, gk=k0+kk;
                rb[i] = (gn<Ncol && gk<Kd) ? Bp[(size_t)gn*ldb+gk] : 0.f;
            }
        } else {
            #pragma unroll
            for(int i=0;i<8;i++){
                int e = tid + 256*i;
                int nn=e%BN, kk=e/BN;
                int gn=n0+nn, gk=k0+kk;
                rb[i] = (gn<Ncol && gk<Kd) ? Bp[(size_t)gk*ldb+gn] : 0.f;
            }
        }
    };
    auto store = [&](int buf){
        #pragma unroll
        for(int i=0;i<8;i++){
            int e = tid + 256*i;
            As[buf][e%BK][e/BK] = ra[i];
        }
        if(!BT){
            #pragma unroll
            for(int i=0;i<8;i++){
                int e = tid + 256*i;
                Bs[buf][e%BK][e/BK] = rb[i];
            }
        } else {
            #pragma unroll
            for(int i=0;i<8;i++){
                int e = tid + 256*i;
                Bs[buf][e/BN][e%BN] = rb[i];
            }
        }
    };

    int nk = (Kd + BK - 1)/BK;
    fetchA(0); fetchB(0);
    store(0);
    __syncthreads();

    for(int t=0;t<nk;t++){
        int cur = t&1;
        if(t+1<nk){ fetchA((t+1)*BK); fetchB((t+1)*BK); }
        #pragma unroll
        for(int kk=0;kk<BK;kk++){   // ascending k, FMA, single accumulator
            float a8[8], b8[8];
            #pragma unroll
            for(int i=0;i<8;i++) a8[i]=As[cur][kk][ty*8+i];
            #pragma unroll
            for(int j=0;j<8;j++) b8[j]=Bs[cur][kk][tx*8+j];
            #pragma unroll
            for(int i=0;i<8;i++)
                #pragma unroll
                for(int j=0;j<8;j++) acc[i][j] = __fmaf_rn(a8[i], b8[j], acc[i][j]);
        }
        if(t+1<nk){
            __syncthreads();
            store(1-cur);
            __syncthreads();
        }
    }

    #pragma unroll
    for(int i=0;i<8;i++){
        int gm = m0+ty*8+i;
        if(gm>=M) continue;
        #pragma unroll
        for(int j=0;j<8;j++){
            int gn = n0+tx*8+j;
            if(gn>=Ncol) continue;
            float v = acc[i][j];
            if(MODE==1)
                v = __fsub_rn(__fsub_rn(__fmul_rn(2.0f, v), e0[(size_t)b*NN+gm]), e0[(size_t)b*NN+gn]);
            else if(MODE==2)
                v = __fadd_rn(v, e0[(size_t)b*M+gm]);
            Cp[(size_t)gm*Ncol + gn] = v;
        }
    }
}

// ------------------------- small kernels -------------------------

__global__ void k_tin(const float* __restrict__ x){
    int i = blockIdx.x*blockDim.x + threadIdx.x;
    if(i >= BB*NN*3) return;
    int c = i%3; int n = (i/3)%NN; int b = i/(3*NN);
    g_xT[i] = x[((size_t)b*3 + c)*NN + n];
}

// per-point squared norm: ascending c, mul then add (ref lowering order)
__global__ void k_xx(int C){
    int p = blockIdx.x*blockDim.x + threadIdx.x;
    if(p >= BB*NN) return;
    const float* v = g_xT + (size_t)p*C;
    float s = 0.f;
    for(int c=0;c<C;c++) s = __fadd_rn(s, __fmul_rn(v[c], v[c]));
    g_xx[p] = s;
}

// register-resident top-K (largest, min-index tiebreak). 256 thr, 8 vals each.
__global__ void __launch_bounds__(256) k_topk(){
    int n = blockIdx.x, b = blockIdx.y;
    const float* row = g_dist + ((size_t)b*NN + n)*NN;
    int tid = threadIdx.x;
    int lane = tid&31, warp = tid>>5;
    float v[8];
    {
        const float4* r4 = (const float4*)(row + tid*8);
        float4 q0 = r4[0], q1 = r4[1];
        v[0]=q0.x; v[1]=q0.y; v[2]=q0.z; v[3]=q0.w;
        v[4]=q1.x; v[5]=q1.y; v[6]=q1.z; v[7]=q1.w;
    }
    __shared__ float swv[8];
    __shared__ int   swi[8];
    __shared__ int   winner;

    for(int j=0;j<KNB;j++){
        // local arg-max over 8 regs (ascending slot keeps min index on ties)
        float bv = v[0]; int bs = 0;
        #pragma unroll
        for(int t=1;t<8;t++) if(v[t]>bv){ bv=v[t]; bs=t; }
        int gi = tid*8 + bs;
        // warp arg-max with min-index tiebreak
        #pragma unroll
        for(int o=16;o;o>>=1){
            float v2 = __shfl_xor_sync(0xffffffffu, bv, o);
            int   i2 = __shfl_xor_sync(0xffffffffu, gi, o);
            if(v2>bv || (v2==bv && i2<gi)){ bv=v2; gi=i2; }
        }
        if(lane==0){ swv[warp]=bv; swi[warp]=gi; }
        __syncthreads();
        if(tid<32){
            float fv = (tid<8)? swv[tid] : -FLT_MAX;
            int   fi = (tid<8)? swi[tid] : NN;
            #pragma unroll
            for(int o=4;o;o>>=1){
                float v2=__shfl_xor_sync(0xffffffffu, fv, o);
                int   i2=__shfl_xor_sync(0xffffffffu, fi, o);
                if(v2>fv || (v2==fv && i2<fi)){ fv=v2; fi=i2; }
            }
            if(tid==0){
                g_idx[((size_t)b*NN+n)*KNB + j] = fi;
                winner = fi;
            }
        }
        __syncthreads();
        int wi = winner;
        if((wi>>3)==tid) v[wi&7] = -FLT_MAX;
    }
}

// G[b, n*K+k, :] = [ xT[idx] - xT[n] (C), xT[n] (C) ]
__global__ void k_gather(int C){
    int C2 = 2*C;
    size_t e = (size_t)blockIdx.x*blockDim.x + threadIdx.x;
    size_t total = (size_t)BB*NN*KNB*C2;
    if(e>=total) return;
    int c = (int)(e % C2);
    size_t r = e / C2;
    int k = (int)(r % KNB);
    int n = (int)((r/KNB) % NN);
    int b = (int)(r/((size_t)KNB*NN));
    int cc = (c < C) ? c : (c - C);
    float ctr = g_xT[((size_t)b*NN + n)*C + cc];
    float val;
    if(c < C){
        int m = g_idx[((size_t)b*NN+n)*KNB + k];
        val = __fsub_rn(g_xT[((size_t)b*NN + m)*C + cc], ctr);
    } else {
        val = ctr;
    }
    g_G[e] = val;
}

// reduce k -> max/min/sum/sumsq; vectorized loads, same ascending-k op order
__global__ void k_kreduce(const float* __restrict__ s, int O){
    size_t p = (size_t)blockIdx.x*blockDim.x + threadIdx.x;
    size_t total = (size_t)BB*O*NN;
    if(p>=total) return;
    const float4* sp = (const float4*)(s + p*KNB);
    float h[KNB];
    #pragma unroll
    for(int q=0;q<5;q++){
        float4 f = sp[q];
        h[q*4+0]=f.x; h[q*4+1]=f.y; h[q*4+2]=f.z; h[q*4+3]=f.w;
    }
    float mx=-FLT_MAX, mn=FLT_MAX, sm=0.f, sq=0.f;
    #pragma unroll
    for(int k=0;k<KNB;k++){
        float hv = h[k];
        mx = fmaxf(mx,hv); mn = fminf(mn,hv);
        sm = __fadd_rn(sm,hv); sq = __fmaf_rn(hv,hv,sq);
    }
    g_kmax[p]=mx; g_kmin[p]=mn; g_ksum[p]=sm; g_ksq[p]=sq;
}

__global__ void k_ec_stats(int O){
    int o = blockIdx.x, tid = threadIdx.x;
    double s=0.0, ss=0.0;
    for(int b=0;b<BB;b++){
        size_t base = ((size_t)b*O + o)*NN;
        for(int n=tid;n<NN;n+=256){ s += g_ksum[base+n]; ss += g_ksq[base+n]; }
    }
    __shared__ double rs[256], rq[256];
    rs[tid]=s; rq[tid]=ss; __syncthreads();
    for(int st=128;st;st>>=1){ if(tid<st){ rs[tid]+=rs[tid+st]; rq[tid]+=rq[tid+st]; } __syncthreads(); }
    if(tid==0){
        double cnt = (double)BB*NN*KNB;
        double mean = rs[0]/cnt;
        double var  = rq[0]/cnt - mean*mean;
        g_prm[2*o]   = (float)mean;
        g_prm[2*o+1] = (float)var;
    }
}

__global__ void k_ec_apply(int O, int c0, float* __restrict__ xTout,
                           const float* __restrict__ gw, const float* __restrict__ bw){
    int o = blockIdx.x, b = blockIdx.y;
    float m = g_prm[2*o], vv = g_prm[2*o+1];
    float gg = gw[o], bb = bw[o];
    float sd = __fsqrt_rn(__fadd_rn(vv, EPSB));
    const float* src = (gg>=0.f ? g_kmax : g_kmin) + ((size_t)b*O + o)*NN;
    float* xc = g_xcat + ((size_t)b*512 + c0 + o)*NN;
    for(int n=threadIdx.x;n<NN;n+=blockDim.x){
        float y = __fadd_rn(__fmul_rn(__fdiv_rn(__fsub_rn(src[n], m), sd), gg), bb);
        y = (y>=0.f) ? y : __fmul_rn(NEGS, y);
        xc[n] = y;
        xTout[((size_t)b*NN + n)*O + o] = y;
    }
}

__global__ void k_conv_stats(const float* __restrict__ h, int O){
    int o = blockIdx.x, tid = threadIdx.x;
    double s=0.0, ss=0.0;
    for(int b=0;b<BB;b++){
        size_t base = ((size_t)b*O + o)*NN;
        for(int n=tid;n<NN;n+=256){ float v=h[base+n]; s += v; ss += (double)v*v; }
    }
    __shared__ double rs[256], rq[256];
    rs[tid]=s; rq[tid]=ss; __syncthreads();
    for(int st=128;st;st>>=1){ if(tid<st){ rs[tid]+=rs[tid+st]; rq[tid]+=rq[tid+st]; } __syncthreads(); }
    if(tid==0){
        double cnt = (double)BB*NN;
        double mean = rs[0]/cnt;
        double var  = rq[0]/cnt - mean*mean;
        g_prm[2*o]   = (float)mean;
        g_prm[2*o+1] = (float)var;
    }
}

__global__ void k_conv_apply(float* __restrict__ h, int O,
                             const float* __restrict__ gw, const float* __restrict__ bw){
    int o = blockIdx.x, b = blockIdx.y;
    float m = g_prm[2*o], vv = g_prm[2*o+1];
    float gg = gw[o], bb = bw[o];
    float sd = __fsqrt_rn(__fadd_rn(vv, EPSB));
    float* p = h + ((size_t)b*O + o)*NN;
    for(int n=threadIdx.x;n<NN;n+=blockDim.x){
        float y = __fadd_rn(__fmul_rn(__fdiv_rn(__fsub_rn(p[n], m), sd), gg), bb);
        p[n] = (y>=0.f) ? y : __fmul_rn(NEGS, y);
    }
}

__global__ void k_gmax(const float* __restrict__ gw, const float* __restrict__ bw){
    int o = blockIdx.x, b = blockIdx.y, tid = threadIdx.x;
    float gg = gw[o];
    const float* p = g_h5 + ((size_t)b*1024 + o)*NN;
    float m = -FLT_MAX, mn = FLT_MAX;
    for(int n=tid;n<NN;n+=256){
        float v = p[n];
        m = fmaxf(m, v); mn = fminf(mn, v);
    }
    __shared__ float r[256], r2[256];
    r[tid]=m; r2[tid]=mn; __syncthreads();
    for(int st=128;st;st>>=1){
        if(tid<st){ r[tid]=fmaxf(r[tid], r[tid+st]); r2[tid]=fminf(r2[tid], r2[tid+st]); }
        __syncthreads();
    }
    if(tid==0){
        float src = (gg>=0.f) ? r[0] : r2[0];
        float mm = g_prm[2*o], vv = g_prm[2*o+1];
        float sd = __fsqrt_rn(__fadd_rn(vv, EPSB));
        float y = __fadd_rn(__fmul_rn(__fdiv_rn(__fsub_rn(src, mm), sd), gg), bw[o]);
        y = (y>=0.f) ? y : __fmul_rn(NEGS, y);
        g_glob[b*1088 + o] = y;
    }
}

__global__ void k_lf(const float* __restrict__ l, const float* __restrict__ W,
                     const float* __restrict__ gw, const float* __restrict__ bw){
    int tid = threadIdx.x;
    int o = tid & 63, b = tid >> 6;
    __shared__ float hs[8][64];
    __shared__ float pm[64], pv[64];
    float s = 0.f;
    #pragma unroll
    for(int c=0;c<16;c++) s = __fmaf_rn(W[o*16 + c], l[b*16 + c], s);
    hs[b][o] = s;
    __syncthreads();
    if(tid < 64){
        float m = 0.f;
        #pragma unroll
        for(int q=0;q<8;q++) m = __fadd_rn(m, hs[q][tid]);
        m = __fdiv_rn(m, 8.f);
        float v = 0.f;
        #pragma unroll
        for(int q=0;q<8;q++){ float d = __fsub_rn(hs[q][tid], m); v = __fmaf_rn(d, d, v); }
        v = __fdiv_rn(v, 8.f);
        pm[tid] = m; pv[tid] = v;
    }
    __syncthreads();
    float sd = __fsqrt_rn(__fadd_rn(pv[o], EPSB));
    float y = __fadd_rn(__fmul_rn(__fdiv_rn(__fsub_rn(hs[b][o], pm[o]), sd), gw[o]), bw[o]);
    y = (y>=0.f) ? y : __fmul_rn(NEGS, y);
    g_glob[b*1088 + 1024 + o] = y;
}

__global__ void k_bias207(const float* __restrict__ W207){
    int b = blockIdx.x;
    __shared__ float gl[1088];
    for(int i=threadIdx.x;i<1088;i+=256) gl[i] = g_glob[b*1088 + i];
    __syncthreads();
    int o = threadIdx.x;
    float s = 0.f;
    for(int c=0;c<1088;c++) s = __fmaf_rn(W207[(size_t)o*1600 + c], gl[c], s);
    g_b207[b*256 + o] = s;
}

// ------------------------- launcher -------------------------
extern "C" void kernel_launch(void* const* d_in, const int* in_sizes, int n_in,
                              void* d_out, int out_size){
    (void)in_sizes; (void)n_in; (void)out_size;
    const float* x    = (const float*)d_in[0];
    const float* l    = (const float*)d_in[1];
    const float* Wec[4] = {(const float*)d_in[2],(const float*)d_in[5],(const float*)d_in[8],(const float*)d_in[11]};
    const float* gec[4] = {(const float*)d_in[3],(const float*)d_in[6],(const float*)d_in[9],(const float*)d_in[12]};
    const float* bec[4] = {(const float*)d_in[4],(const float*)d_in[7],(const float*)d_in[10],(const float*)d_in[13]};
    const float* W5   = (const float*)d_in[14]; const float* g5v  = (const float*)d_in[15]; const float* b5v  = (const float*)d_in[16];
    const float* W206 = (const float*)d_in[17]; const float* g206 = (const float*)d_in[18]; const float* b206 = (const float*)d_in[19];
    const float* W207 = (const float*)d_in[20]; const float* g207 = (const float*)d_in[21]; const float* b207 = (const float*)d_in[22];
    const float* W208 = (const float*)d_in[23]; const float* g208 = (const float*)d_in[24]; const float* b208 = (const float*)d_in[25];
    const float* W209 = (const float*)d_in[26]; const float* g209 = (const float*)d_in[27]; const float* b209 = (const float*)d_in[28];
    const float* W2010= (const float*)d_in[29];

    float *xT,*xxp,*dist,*G,*sbuf,*xcat,*h5,*hb1,*hb2,*hb3,*b207p;
    cudaGetSymbolAddress((void**)&xT,   g_xT);
    cudaGetSymbolAddress((void**)&xxp,  g_xx);
    cudaGetSymbolAddress((void**)&dist, g_dist);
    cudaGetSymbolAddress((void**)&G,    g_G);
    cudaGetSymbolAddress((void**)&sbuf, g_s);
    cudaGetSymbolAddress((void**)&xcat, g_xcat);
    cudaGetSymbolAddress((void**)&h5,   g_h5);
    cudaGetSymbolAddress((void**)&hb1,  g_hb1);
    cudaGetSymbolAddress((void**)&hb2,  g_hb2);
    cudaGetSymbolAddress((void**)&hb3,  g_hb3);
    cudaGetSymbolAddress((void**)&b207p,g_b207);

    const int Cin[4] = {3,64,64,128};
    const int Oo [4] = {64,64,128,256};
    const int c0 [4] = {0,64,128,256};

    k_tin<<<(BB*NN*3 + 255)/256, 256>>>(x);

    for(int li=0; li<4; li++){
        int C = Cin[li], O = Oo[li];
        k_xx<<<(BB*NN + 255)/256, 256>>>(C);
        k_gemm<false,1><<<dim3(NN/128, NN/128, BB), 256>>>(
            NN, NN, C, xT, C, (size_t)NN*C, xT, C, (size_t)NN*C, dist, (size_t)NN*NN, xxp);
        k_topk<<<dim3(NN, BB), 256>>>();
        int C2 = 2*C;
        size_t tot = (size_t)BB*NN*KNB*C2;
        k_gather<<<(unsigned)((tot + 255)/256), 256>>>(C);
        int J = NN*KNB;
        k_gemm<false,0><<<dim3(J/128, (O+127)/128, BB), 256>>>(
            O, J, C2, Wec[li], C2, 0, G, C2, (size_t)J*C2, sbuf, (size_t)O*J, nullptr);
        size_t tp = (size_t)BB*O*NN;
        k_kreduce<<<(unsigned)((tp + 255)/256), 256>>>(sbuf, O);
        k_ec_stats<<<O, 256>>>(O);
        k_ec_apply<<<dim3(O, BB), 256>>>(O, c0[li], xT, gec[li], bec[li]);
    }

    k_gemm<true,0><<<dim3(NN/128, 1024/128, BB), 256>>>(
        1024, NN, 512, W5, 512, 0, xcat, NN, (size_t)512*NN, h5, (size_t)1024*NN, nullptr);
    k_conv_stats<<<1024, 256>>>(h5, 1024);
    k_gmax<<<dim3(1024, BB), 256>>>(g5v, b5v);
    k_lf<<<1, 512>>>(l, W206, g206, b206);
    k_bias207<<<BB, 256>>>(W207);
    k_gemm<true,2><<<dim3(NN/128, 2, BB), 256>>>(
        256, NN, 512, W207 + 1088, 1600, 0, xcat, NN, (size_t)512*NN, hb1, (size_t)256*NN, b207p);
    k_conv_stats<<<256, 256>>>(hb1, 256);
    k_conv_apply<<<dim3(256, BB), 256>>>(hb1, 256, g207, b207);
    k_gemm<true,0><<<dim3(NN/128, 2, BB), 256>>>(
        256, NN, 256, W208, 256, 0, hb1, NN, (size_t)256*NN, hb2, (size_t)256*NN, nullptr);
    k_conv_stats<<<256, 256>>>(hb2, 256);
    k_conv_apply<<<dim3(256, BB), 256>>>(hb2, 256, g208, b208);
    k_gemm<true,0><<<dim3(NN/128, 1, BB), 256>>>(
        128, NN, 256, W209, 256, 0, hb2, NN, (size_t)256*NN, hb3, (size_t)128*NN, nullptr);
    k_conv_stats<<<128, 256>>>(hb3, 128);
    k_conv_apply<<<dim3(128, BB), 256>>>(hb3, 128, g209, b209);
    k_gemm<true,0><<<dim3(NN/128, 1, BB), 256>>>(
        50, NN, 128, W2010, 128, 0, hb3, NN, (size_t)128*NN, (float*)d_out, (size_t)50*NN, nullptr);
}